// round 15
// baseline (speedup 1.0000x reference)
#include <cuda_runtime.h>
#include <cuda_fp16.h>
#include <math.h>
#include <cstdint>

#define BATCH   8
#define SEQ     2048
#define EMB     768
#define NHEADS  12
#define HDIM    64
#define BS_TOT  (BATCH * SEQ)      // 16384

// Scratch (alloc-free rules)
__device__ __half g_x [BS_TOT * EMB];   // x converted to half
__device__ __half g_wq[EMB * EMB];      // W_Q^T: [n*64+h][e]
__device__ __half g_wk[EMB * EMB];
__device__ __half g_wv[EMB * EMB];
__device__ __half g_wo[EMB * EMB];      // W_O^T: [e][n*64+h]
__device__ __half g_q [BS_TOT * EMB];
__device__ __half g_k [BS_TOT * EMB];
__device__ __half g_v [BS_TOT * EMB];
__device__ __half g_z [BS_TOT * EMB];

// ===========================================================================
// Helpers (fp16 m16n8k16 mma, ldmatrix, cp.async; no tcgen05 on compute_103)
// ===========================================================================
__device__ __forceinline__ uint32_t packh2(float lo, float hi) {
    __half2 h = __floats2half2_rn(lo, hi);
    return *(uint32_t*)&h;
}

__device__ __forceinline__ float ex2f(float x) {
    float y;
    asm("ex2.approx.ftz.f32 %0, %1;" : "=f"(y) : "f"(x));
    return y;
}

__device__ __forceinline__ void mma_f16(float* d, const uint32_t* a,
                                        const uint32_t* b) {
    asm volatile(
        "mma.sync.aligned.m16n8k16.row.col.f32.f16.f16.f32 "
        "{%0,%1,%2,%3}, {%4,%5,%6,%7}, {%8,%9}, {%0,%1,%2,%3};"
        : "+f"(d[0]), "+f"(d[1]), "+f"(d[2]), "+f"(d[3])
        : "r"(a[0]), "r"(a[1]), "r"(a[2]), "r"(a[3]),
          "r"(b[0]), "r"(b[1]));
}

__device__ __forceinline__ void ldmatrix_x4(uint32_t* r, uint32_t addr) {
    asm volatile(
        "ldmatrix.sync.aligned.m8n8.x4.shared.b16 {%0,%1,%2,%3}, [%4];"
        : "=r"(r[0]), "=r"(r[1]), "=r"(r[2]), "=r"(r[3]) : "r"(addr));
}
__device__ __forceinline__ void ldmatrix_x4_trans(uint32_t* r, uint32_t addr) {
    asm volatile(
        "ldmatrix.sync.aligned.m8n8.x4.trans.shared.b16 {%0,%1,%2,%3}, [%4];"
        : "=r"(r[0]), "=r"(r[1]), "=r"(r[2]), "=r"(r[3]) : "r"(addr));
}

__device__ __forceinline__ uint32_t smem_u32(const void* p) {
    uint32_t a;
    asm("{ .reg .u64 t; cvta.to.shared.u64 t, %1; cvt.u32.u64 %0, t; }"
        : "=r"(a) : "l"(p));
    return a;
}

#define CP_ASYNC16(sa, gp) \
    asm volatile("cp.async.cg.shared.global [%0], [%1], 16;" \
        :: "r"(sa), "l"(gp))
#define CP_COMMIT() asm volatile("cp.async.commit_group;")
#define CP_WAIT(n)  asm volatile("cp.async.wait_group %0;" :: "n"(n))

// ===========================================================================
// Prep kernels: convert x, transpose+convert weights (run once per launch)
// ===========================================================================
__global__ __launch_bounds__(256) void cvt_x(const float* __restrict__ x) {
    int i = blockIdx.x * 256 + threadIdx.x;          // per float4
    float4 v = ((const float4*)x)[i];
    ((uint2*)g_x)[i] = make_uint2(packh2(v.x, v.y), packh2(v.z, v.w));
}

// W [n][e][h] fp32 -> Wt [n*64+h][e] half.  grid (2, 24, 12), block (32, 8).
__global__ void tr_qkv(const float* __restrict__ W, __half* __restrict__ Wt) {
    __shared__ float t[32][33];
    const int n = blockIdx.z, h0 = blockIdx.x * 32, e0 = blockIdx.y * 32;
    const int tx = threadIdx.x, ty = threadIdx.y;
#pragma unroll
    for (int j = 0; j < 4; j++)
        t[ty + 8 * j][tx] = W[((size_t)n * EMB + e0 + ty + 8 * j) * 64 + h0 + tx];
    __syncthreads();
#pragma unroll
    for (int j = 0; j < 4; j++)
        Wt[((size_t)n * 64 + h0 + ty + 8 * j) * EMB + e0 + tx] =
            __float2half(t[tx][ty + 8 * j]);
}

// W [k][e] fp32 -> Wt [e][k] half.  grid (24, 24), block (32, 8).
__global__ void tr_wo(const float* __restrict__ W) {
    __shared__ float t[32][33];
    const int k0 = blockIdx.x * 32, e0 = blockIdx.y * 32;
    const int tx = threadIdx.x, ty = threadIdx.y;
#pragma unroll
    for (int j = 0; j < 4; j++)
        t[ty + 8 * j][tx] = W[(size_t)(k0 + ty + 8 * j) * EMB + e0 + tx];
    __syncthreads();
#pragma unroll
    for (int j = 0; j < 4; j++)
        g_wo[(size_t)(e0 + ty + 8 * j) * EMB + k0 + tx] =
            __float2half(t[tx][ty + 8 * j]);
}

// ===========================================================================
// Half GEMM body: acc[128x128] = A[M,768] @ B[N,768]^T, 3-stage cp.async.
// 256 threads, 8 warps (wr in 0..1 -> 64 m-rows, wc in 0..3 -> 32 n-cols).
// ===========================================================================
#define GPH   40                      // half pitch (80B = 5x16B)
#define STAGE_H (2 * 128 * GPH)       // halves per stage (A+B)
#define NST   (EMB / 32)              // 24
#define GEMM_SMEM (3 * STAGE_H * 2)   // 61440 B

__device__ __forceinline__ void gemm_body(
    const __half* __restrict__ A, const __half* __restrict__ B,
    __half* smem, float acc[4][4][4], int m0, int n0)
{
    const int tid = threadIdx.x;
    const int wid = tid >> 5, lane = tid & 31;
    const int wr = wid >> 2, wc = wid & 3;
    const int lmro = (lane & 7) + ((lane >> 3) & 1) * 8;
    const int lmco = (lane >> 4) * 8;
    const int b_nt = (lane >> 4), b_kh = (lane >> 3) & 1;
    const int b_ro = lane & 7;
    const int lrow = tid >> 2, loc = tid & 3;   // cp.async mapping

    const uint32_t smb = smem_u32(smem);

    auto issue = [&](int s) {
        const int k0 = s * 32;
        const uint32_t st = smb + (s % 3) * (STAGE_H * 2);
#pragma unroll
        for (int i = 0; i < 2; i++) {
            int row = lrow + i * 64;
            CP_ASYNC16(st + 2 * (row * GPH + loc * 8),
                       A + (size_t)(m0 + row) * EMB + k0 + loc * 8);
            CP_ASYNC16(st + 2 * (128 * GPH + row * GPH + loc * 8),
                       B + (size_t)(n0 + row) * EMB + k0 + loc * 8);
        }
        CP_COMMIT();
    };

    issue(0);
    issue(1);

    for (int s = 0; s < NST; s++) {
        if (s + 2 < NST) { CP_WAIT(1); } else { CP_WAIT(0); }
        __syncthreads();
        if (s + 2 < NST) issue(s + 2);

        const uint32_t st = smb + (s % 3) * (STAGE_H * 2);
        const uint32_t a_base = st + 2 * ((wr * 64 + lmro) * GPH + lmco);
        const uint32_t b_base = st + 2 * (128 * GPH +
                                (wc * 32 + b_nt * 8 + b_ro) * GPH + b_kh * 8);
#pragma unroll
        for (int ks = 0; ks < 2; ks++) {
            const int k0 = ks * 16;
            uint32_t af[4][4], bf[4][2];
#pragma unroll
            for (int mt = 0; mt < 4; mt++)
                ldmatrix_x4(af[mt], a_base + 2 * (mt * 16 * GPH + k0));
#pragma unroll
            for (int p = 0; p < 2; p++) {
                uint32_t r[4];
                ldmatrix_x4(r, b_base + 2 * (p * 16 * GPH + k0));
                bf[2 * p][0] = r[0];     bf[2 * p][1] = r[1];
                bf[2 * p + 1][0] = r[2]; bf[2 * p + 1][1] = r[3];
            }
#pragma unroll
            for (int mt = 0; mt < 4; mt++)
#pragma unroll
                for (int nt = 0; nt < 4; nt++)
                    mma_f16(acc[mt][nt], af[mt], bf[nt]);
        }
    }
}

// QKV projection: half in/out, Q scaled by (1/8)*log2(e) in epilogue
// (attention softmax runs in the exp2 domain).
__global__ __launch_bounds__(256) void gemm_qkv(
    const float* __restrict__ bQ, const float* __restrict__ bK,
    const float* __restrict__ bV)
{
    extern __shared__ __half smem[];
    const __half* Bm = (blockIdx.z == 0) ? g_wq : (blockIdx.z == 1) ? g_wk : g_wv;
    const float* bias = (blockIdx.z == 0) ? bQ : (blockIdx.z == 1) ? bK : bV;
    __half* C = (blockIdx.z == 0) ? g_q : (blockIdx.z == 1) ? g_k : g_v;
    const float qs = (blockIdx.z == 0) ? 0.125f * 1.44269504f : 1.0f;
    const int m0 = blockIdx.y * 128, n0 = blockIdx.x * 128;

    float acc[4][4][4];
#pragma unroll
    for (int mt = 0; mt < 4; mt++)
#pragma unroll
        for (int nt = 0; nt < 4; nt++)
#pragma unroll
            for (int i = 0; i < 4; i++) acc[mt][nt][i] = 0.f;

    gemm_body(g_x, Bm, smem, acc, m0, n0);

    const int lane = threadIdx.x & 31, wid = threadIdx.x >> 5;
    const int wr = wid >> 2, wc = wid & 3;
    const int gr = lane >> 2, tg = lane & 3;
#pragma unroll
    for (int mt = 0; mt < 4; mt++)
#pragma unroll
        for (int nt = 0; nt < 4; nt++) {
            int r = m0 + wr * 64 + mt * 16 + gr;
            int c = n0 + wc * 32 + nt * 8 + tg * 2;
            float b0 = bias[c], b1 = bias[c + 1];
            *(uint32_t*)&C[(size_t)r * EMB + c] =
                packh2((acc[mt][nt][0] + b0) * qs, (acc[mt][nt][1] + b1) * qs);
            *(uint32_t*)&C[(size_t)(r + 8) * EMB + c] =
                packh2((acc[mt][nt][2] + b0) * qs, (acc[mt][nt][3] + b1) * qs);
        }
}

// Output projection: z (half) @ WO^T -> fp32 out + bias.
__global__ __launch_bounds__(256) void gemm_wo(
    const float* __restrict__ bias, float* __restrict__ C)
{
    extern __shared__ __half smem[];
    const int m0 = blockIdx.y * 128, n0 = blockIdx.x * 128;

    float acc[4][4][4];
#pragma unroll
    for (int mt = 0; mt < 4; mt++)
#pragma unroll
        for (int nt = 0; nt < 4; nt++)
#pragma unroll
            for (int i = 0; i < 4; i++) acc[mt][nt][i] = 0.f;

    gemm_body(g_z, g_wo, smem, acc, m0, n0);

    const int lane = threadIdx.x & 31, wid = threadIdx.x >> 5;
    const int wr = wid >> 2, wc = wid & 3;
    const int gr = lane >> 2, tg = lane & 3;
#pragma unroll
    for (int mt = 0; mt < 4; mt++)
#pragma unroll
        for (int nt = 0; nt < 4; nt++) {
            int r = m0 + wr * 64 + mt * 16 + gr;
            int c = n0 + wc * 32 + nt * 8 + tg * 2;
            float b0 = bias[c], b1 = bias[c + 1];
            *(float2*)(C + (size_t)r * EMB + c) =
                make_float2(acc[mt][nt][0] + b0, acc[mt][nt][1] + b1);
            *(float2*)(C + (size_t)(r + 8) * EMB + c) =
                make_float2(acc[mt][nt][2] + b0, acc[mt][nt][3] + b1);
        }
}

// ===========================================================================
// Flash attention (causal), fp16 m16n8k16, register softmax in exp2 domain,
// all-ldmatrix, cp.async double-buffered 64-KEY tiles with per-8-key group
// causal skipping.  Block = (b, head, 128-query tile), 128 thr, 4 warps.
// ===========================================================================
#define AP 72   // half pitch (144B = 9x16B)

__global__ __launch_bounds__(128) void attn_tc()
{
    __shared__ __half sbuf[256 * AP];   // 36.9 KB: 2 x (64K + 64V) buffers
    const __half* q = g_q; const __half* k = g_k; const __half* v = g_v;

    const int tid = threadIdx.x;
    const int w = tid >> 5, lane = tid & 31;
    const int gr = lane >> 2, tg = lane & 3;
    const int qt = gridDim.x - 1 - blockIdx.x;      // LPT: big tiles first
    const int hn = blockIdx.y, b = blockIdx.z;
    const int q_base = qt * 128;
    const size_t base_bn = (size_t)b * SEQ * EMB + (size_t)hn * HDIM;

    const int lmro = (lane & 7) + ((lane >> 3) & 1) * 8;
    const int lmco = (lane >> 4) * 8;
    const int b_nt = (lane >> 4), b_kh = (lane >> 3) & 1;
    const int b_ro = lane & 7;

    // ---- Q phase: gmem -> smem rows 0..127 -> A-frags via ldmatrix ----
#pragma unroll
    for (int i = 0; i < 8; i++) {
        int idx = tid + i * 128;
        int row = idx >> 3, oc = idx & 7;
        *(uint4*)&sbuf[row * AP + oc * 8] =
            *(const uint4*)(q + base_bn + (size_t)(q_base + row) * EMB + oc * 8);
    }
    __syncthreads();
    uint32_t qf[2][4][4];
    {
        const uint32_t qb = smem_u32(sbuf) + 2 * ((w * 32 + lmro) * AP + lmco);
#pragma unroll
        for (int mt = 0; mt < 2; mt++)
#pragma unroll
            for (int ks = 0; ks < 4; ks++)
                ldmatrix_x4(qf[mt][ks], qb + 2 * (mt * 16 * AP + ks * 16));
    }
    __syncthreads();

    const uint32_t sbu = smem_u32(sbuf);
    const int lm_row = ((lane >> 3) & 1) * 8 + (lane & 7);
    const int lm_col = (lane >> 4) * 8;

    const int wrow = q_base + w * 32;
    const int nkt = 2 * qt + 2;     // 64-wide key tiles

    // cp.async: 64 rows K + 64 rows V per tile; 8 chunks(16B) per thread.
    auto issue_kv = [&](int kt) {
        const uint32_t bb = sbu + (kt & 1) * (128 * AP * 2);
#pragma unroll
        for (int i = 0; i < 4; i++) {
            int idx = tid + i * 128;
            int row = idx >> 3, oc = idx & 7;
            const size_t g = base_bn + (size_t)(kt * 64 + row) * EMB + oc * 8;
            CP_ASYNC16(bb + 2 * (row * AP + oc * 8), k + g);
            CP_ASYNC16(bb + 2 * ((64 + row) * AP + oc * 8), v + g);
        }
        CP_COMMIT();
    };

    float o[2][8][4];
#pragma unroll
    for (int mt = 0; mt < 2; mt++)
#pragma unroll
        for (int nt = 0; nt < 8; nt++)
#pragma unroll
            for (int i = 0; i < 4; i++) o[mt][nt][i] = 0.f;

    float mX[2][2] = {{-INFINITY, -INFINITY}, {-INFINITY, -INFINITY}};
    float lX[2][2] = {{0.f, 0.f}, {0.f, 0.f}};

    issue_kv(0);

    for (int kt = 0; kt < nkt; kt++) {
        CP_WAIT(0);
        __syncthreads();
        if (kt + 1 < nkt) issue_kv(kt + 1);

        if (kt * 64 <= wrow + 31) {   // warp-uniform causal skip (whole tile)
            const int rel = wrow + 31 - kt * 64;   // last useful key offset
            const uint32_t kbase = sbu + (kt & 1) * (128 * AP * 2);
            const uint32_t ks_frag_base =
                kbase + 2 * ((b_nt * 8 + b_ro) * AP + b_kh * 8);
            const uint32_t vs_base = kbase + 2 * (64 * AP);

            // ---- scores (skip fully-masked 16-key column groups) ----
            float sc[2][8][4];
#pragma unroll
            for (int mt = 0; mt < 2; mt++)
#pragma unroll
                for (int nt = 0; nt < 8; nt++)
#pragma unroll
                    for (int i = 0; i < 4; i++) sc[mt][nt][i] = 0.f;
#pragma unroll
            for (int ks = 0; ks < 4; ks++) {
                uint32_t bf[8][2];
#pragma unroll
                for (int p = 0; p < 4; p++) {
                    if (p * 16 <= rel) {
                        uint32_t r[4];
                        ldmatrix_x4(r,
                            ks_frag_base + 2 * (p * 16 * AP + ks * 16));
                        bf[2 * p][0] = r[0];     bf[2 * p][1] = r[1];
                        bf[2 * p + 1][0] = r[2]; bf[2 * p + 1][1] = r[3];
                    }
                }
#pragma unroll
                for (int nt = 0; nt < 8; nt++) {
                    if (nt * 8 <= rel) {
                        mma_f16(sc[0][nt], qf[0][ks], bf[nt]);
                        mma_f16(sc[1][nt], qf[1][ks], bf[nt]);
                    }
                }
            }

            // ---- causal mask (diagonal-overlapping tiles only) ----
            if (kt * 64 + 63 > wrow) {
#pragma unroll
                for (int mt = 0; mt < 2; mt++) {
                    const int ig0 = wrow + mt * 16 + gr;
                    const int ig1 = ig0 + 8;
                    const int jb = kt * 64 + tg * 2;
#pragma unroll
                    for (int nt = 0; nt < 8; nt++) {
                        if (nt * 8 <= rel) {
                            int jg = jb + nt * 8;
                            if (jg > ig0)     sc[mt][nt][0] = -1e30f;
                            if (jg + 1 > ig0) sc[mt][nt][1] = -1e30f;
                            if (jg > ig1)     sc[mt][nt][2] = -1e30f;
                            if (jg + 1 > ig1) sc[mt][nt][3] = -1e30f;
                        }
                    }
                }
            }

            // ---- online softmax per m-tile (exp2 domain) ----
            const unsigned FULL = 0xffffffffu;
            float aa[2][2];
#pragma unroll
            for (int mt = 0; mt < 2; mt++) {
                float tm0 = sc[mt][0][0], tm1 = sc[mt][0][2];
#pragma unroll
                for (int nt = 0; nt < 8; nt++) {
                    if (nt * 8 <= rel) {
                        tm0 = fmaxf(tm0, fmaxf(sc[mt][nt][0], sc[mt][nt][1]));
                        tm1 = fmaxf(tm1, fmaxf(sc[mt][nt][2], sc[mt][nt][3]));
                    }
                }
                tm0 = fmaxf(tm0, __shfl_xor_sync(FULL, tm0, 1));
                tm0 = fmaxf(tm0, __shfl_xor_sync(FULL, tm0, 2));
                tm1 = fmaxf(tm1, __shfl_xor_sync(FULL, tm1, 1));
                tm1 = fmaxf(tm1, __shfl_xor_sync(FULL, tm1, 2));

                float mn0 = fmaxf(mX[mt][0], tm0), mn1 = fmaxf(mX[mt][1], tm1);
                float a0 = ex2f(mX[mt][0] - mn0), a1 = ex2f(mX[mt][1] - mn1);
                mX[mt][0] = mn0; mX[mt][1] = mn1;

                float s0 = 0.f, s1 = 0.f;
#pragma unroll
                for (int nt = 0; nt < 8; nt++) {
                    if (nt * 8 <= rel) {
                        float p00 = ex2f(sc[mt][nt][0] - mn0);
                        float p01 = ex2f(sc[mt][nt][1] - mn0);
                        float p10 = ex2f(sc[mt][nt][2] - mn1);
                        float p11 = ex2f(sc[mt][nt][3] - mn1);
                        s0 += p00 + p01; s1 += p10 + p11;
                        sc[mt][nt][0] = p00; sc[mt][nt][1] = p01;
                        sc[mt][nt][2] = p10; sc[mt][nt][3] = p11;
                    }
                }
                s0 += __shfl_xor_sync(FULL, s0, 1);
                s0 += __shfl_xor_sync(FULL, s0, 2);
                s1 += __shfl_xor_sync(FULL, s1, 1);
                s1 += __shfl_xor_sync(FULL, s1, 2);
                lX[mt][0] = lX[mt][0] * a0 + s0;
                lX[mt][1] = lX[mt][1] * a1 + s1;
                aa[mt][0] = a0; aa[mt][1] = a1;
            }

            // ---- rescale O ----
#pragma unroll
            for (int mt = 0; mt < 2; mt++)
#pragma unroll
                for (int nt = 0; nt < 8; nt++) {
                    o[mt][nt][0] *= aa[mt][0]; o[mt][nt][1] *= aa[mt][0];
                    o[mt][nt][2] *= aa[mt][1]; o[mt][nt][3] *= aa[mt][1];
                }

            // ---- O += P @ V (skip fully-masked 16-key row groups) ----
#pragma unroll
            for (int kg = 0; kg < 4; kg++) {
                if (kg * 16 <= rel) {
                    uint32_t af[2][4];
#pragma unroll
                    for (int mt = 0; mt < 2; mt++) {
                        af[mt][0] = packh2(sc[mt][2 * kg][0], sc[mt][2 * kg][1]);
                        af[mt][1] = packh2(sc[mt][2 * kg][2], sc[mt][2 * kg][3]);
                        af[mt][2] = packh2(sc[mt][2 * kg + 1][0], sc[mt][2 * kg + 1][1]);
                        af[mt][3] = packh2(sc[mt][2 * kg + 1][2], sc[mt][2 * kg + 1][3]);
                    }
                    const uint32_t rbase =
                        vs_base + 2 * ((kg * 16 + lm_row) * AP + lm_col);
#pragma unroll
                    for (int pr = 0; pr < 4; pr++) {
                        uint32_t vb[4];
                        ldmatrix_x4_trans(vb, rbase + 2 * (pr * 16));
                        mma_f16(o[0][2 * pr],     af[0], vb);
                        mma_f16(o[0][2 * pr + 1], af[0], vb + 2);
                        mma_f16(o[1][2 * pr],     af[1], vb);
                        mma_f16(o[1][2 * pr + 1], af[1], vb + 2);
                    }
                }
            }
        }
    }

    // ---- normalize & store (half) ----
#pragma unroll
    for (int mt = 0; mt < 2; mt++) {
        const float inv0 = 1.f / lX[mt][0], inv1 = 1.f / lX[mt][1];
        const int r0 = wrow + mt * 16 + gr;
#pragma unroll
        for (int nt = 0; nt < 8; nt++) {
            int d = nt * 8 + tg * 2;
            size_t g0 = base_bn + (size_t)r0 * EMB + d;
            size_t g1 = base_bn + (size_t)(r0 + 8) * EMB + d;
            *(uint32_t*)&g_z[g0] = packh2(o[mt][nt][0] * inv0, o[mt][nt][1] * inv0);
            *(uint32_t*)&g_z[g1] = packh2(o[mt][nt][2] * inv1, o[mt][nt][3] * inv1);
        }
    }
}

// ---------------------------------------------------------------------------
extern "C" void kernel_launch(void* const* d_in, const int* in_sizes, int n_in,
                              void* d_out, int out_size)
{
    const float* x  = (const float*)d_in[0];
    const float* WQ = (const float*)d_in[1];
    const float* WK = (const float*)d_in[2];
    const float* WV = (const float*)d_in[3];
    const float* WO = (const float*)d_in[4];
    const float* bQ = (const float*)d_in[5];
    const float* bK = (const float*)d_in[6];
    const float* bV = (const float*)d_in[7];
    const float* bO = (const float*)d_in[8];
    float* out = (float*)d_out;

    __half *wqp, *wkp, *wvp;
    cudaGetSymbolAddress((void**)&wqp, g_wq);
    cudaGetSymbolAddress((void**)&wkp, g_wk);
    cudaGetSymbolAddress((void**)&wvp, g_wv);

    cudaFuncSetAttribute(gemm_qkv,
        cudaFuncAttributeMaxDynamicSharedMemorySize, GEMM_SMEM);
    cudaFuncSetAttribute(gemm_wo,
        cudaFuncAttributeMaxDynamicSharedMemorySize, GEMM_SMEM);

    // ---- prep: convert x, transpose+convert weights ----
    cvt_x<<<BS_TOT * EMB / 4 / 256, 256>>>(x);
    tr_qkv<<<dim3(2, 24, 12), dim3(32, 8)>>>(WQ, wqp);
    tr_qkv<<<dim3(2, 24, 12), dim3(32, 8)>>>(WK, wkp);
    tr_qkv<<<dim3(2, 24, 12), dim3(32, 8)>>>(WV, wvp);
    tr_wo<<<dim3(24, 24), dim3(32, 8)>>>(WO);

    // ---- main pipeline ----
    gemm_qkv<<<dim3(EMB / 128, BS_TOT / 128, 3), 256, GEMM_SMEM>>>(bQ, bK, bV);
    attn_tc<<<dim3(SEQ / 128, NHEADS, BATCH), 128>>>();
    gemm_wo<<<dim3(EMB / 128, BS_TOT / 128), 256, GEMM_SMEM>>>(bO, out);
}

// round 17
// speedup vs baseline: 1.1279x; 1.1279x over previous
#include <cuda_runtime.h>
#include <cuda_fp16.h>
#include <math.h>
#include <cstdint>

#define BATCH   8
#define SEQ     2048
#define EMB     768
#define NHEADS  12
#define HDIM    64
#define BS_TOT  (BATCH * SEQ)      // 16384

// Scratch (alloc-free rules)
__device__ __half g_x [BS_TOT * EMB];   // x converted to half
__device__ __half g_wq[EMB * EMB];      // W_Q^T: [n*64+h][e]
__device__ __half g_wk[EMB * EMB];
__device__ __half g_wv[EMB * EMB];
__device__ __half g_wo[EMB * EMB];      // W_O^T: [e][n*64+h]
__device__ __half g_q [BS_TOT * EMB];
__device__ __half g_k [BS_TOT * EMB];
__device__ __half g_v [BS_TOT * EMB];
__device__ __half g_z [BS_TOT * EMB];

// ===========================================================================
// Helpers (fp16 m16n8k16 mma, ldmatrix, cp.async; no tcgen05 on compute_103)
// ===========================================================================
__device__ __forceinline__ uint32_t packh2(float lo, float hi) {
    __half2 h = __floats2half2_rn(lo, hi);
    return *(uint32_t*)&h;
}

__device__ __forceinline__ float ex2f(float x) {
    float y;
    asm("ex2.approx.ftz.f32 %0, %1;" : "=f"(y) : "f"(x));
    return y;
}

__device__ __forceinline__ void mma_f16(float* d, const uint32_t* a,
                                        const uint32_t* b) {
    asm volatile(
        "mma.sync.aligned.m16n8k16.row.col.f32.f16.f16.f32 "
        "{%0,%1,%2,%3}, {%4,%5,%6,%7}, {%8,%9}, {%0,%1,%2,%3};"
        : "+f"(d[0]), "+f"(d[1]), "+f"(d[2]), "+f"(d[3])
        : "r"(a[0]), "r"(a[1]), "r"(a[2]), "r"(a[3]),
          "r"(b[0]), "r"(b[1]));
}

__device__ __forceinline__ void ldmatrix_x4(uint32_t* r, uint32_t addr) {
    asm volatile(
        "ldmatrix.sync.aligned.m8n8.x4.shared.b16 {%0,%1,%2,%3}, [%4];"
        : "=r"(r[0]), "=r"(r[1]), "=r"(r[2]), "=r"(r[3]) : "r"(addr));
}
__device__ __forceinline__ void ldmatrix_x4_trans(uint32_t* r, uint32_t addr) {
    asm volatile(
        "ldmatrix.sync.aligned.m8n8.x4.trans.shared.b16 {%0,%1,%2,%3}, [%4];"
        : "=r"(r[0]), "=r"(r[1]), "=r"(r[2]), "=r"(r[3]) : "r"(addr));
}

__device__ __forceinline__ uint32_t smem_u32(const void* p) {
    uint32_t a;
    asm("{ .reg .u64 t; cvta.to.shared.u64 t, %1; cvt.u32.u64 %0, t; }"
        : "=r"(a) : "l"(p));
    return a;
}

#define CP_ASYNC16(sa, gp) \
    asm volatile("cp.async.cg.shared.global [%0], [%1], 16;" \
        :: "r"(sa), "l"(gp))
#define CP_COMMIT() asm volatile("cp.async.commit_group;")
#define CP_WAIT(n)  asm volatile("cp.async.wait_group %0;" :: "n"(n))

// ===========================================================================
// Prep kernels: convert x, transpose+convert weights (run once per launch)
// ===========================================================================
__global__ __launch_bounds__(256) void cvt_x(const float* __restrict__ x) {
    int i = blockIdx.x * 256 + threadIdx.x;          // per float4
    float4 v = ((const float4*)x)[i];
    ((uint2*)g_x)[i] = make_uint2(packh2(v.x, v.y), packh2(v.z, v.w));
}

// W [n][e][h] fp32 -> Wt [n*64+h][e] half.  grid (2, 24, 12), block (32, 8).
__global__ void tr_qkv(const float* __restrict__ W, __half* __restrict__ Wt) {
    __shared__ float t[32][33];
    const int n = blockIdx.z, h0 = blockIdx.x * 32, e0 = blockIdx.y * 32;
    const int tx = threadIdx.x, ty = threadIdx.y;
#pragma unroll
    for (int j = 0; j < 4; j++)
        t[ty + 8 * j][tx] = W[((size_t)n * EMB + e0 + ty + 8 * j) * 64 + h0 + tx];
    __syncthreads();
#pragma unroll
    for (int j = 0; j < 4; j++)
        Wt[((size_t)n * 64 + h0 + ty + 8 * j) * EMB + e0 + tx] =
            __float2half(t[tx][ty + 8 * j]);
}

// W [k][e] fp32 -> Wt [e][k] half.  grid (24, 24), block (32, 8).
__global__ void tr_wo(const float* __restrict__ W) {
    __shared__ float t[32][33];
    const int k0 = blockIdx.x * 32, e0 = blockIdx.y * 32;
    const int tx = threadIdx.x, ty = threadIdx.y;
#pragma unroll
    for (int j = 0; j < 4; j++)
        t[ty + 8 * j][tx] = W[(size_t)(k0 + ty + 8 * j) * EMB + e0 + tx];
    __syncthreads();
#pragma unroll
    for (int j = 0; j < 4; j++)
        g_wo[(size_t)(e0 + ty + 8 * j) * EMB + k0 + tx] =
            __float2half(t[tx][ty + 8 * j]);
}

// ===========================================================================
// Half GEMM body: acc[128x128] = A[M,768] @ B[N,768]^T, 3-stage cp.async.
// 256 threads, 8 warps (wr in 0..1 -> 64 m-rows, wc in 0..3 -> 32 n-cols).
// ===========================================================================
#define GPH   40                      // half pitch (80B = 5x16B)
#define STAGE_H (2 * 128 * GPH)       // halves per stage (A+B)
#define NST   (EMB / 32)              // 24
#define GEMM_SMEM (3 * STAGE_H * 2)   // 61440 B

__device__ __forceinline__ void gemm_body(
    const __half* __restrict__ A, const __half* __restrict__ B,
    __half* smem, float acc[4][4][4], int m0, int n0)
{
    const int tid = threadIdx.x;
    const int wid = tid >> 5, lane = tid & 31;
    const int wr = wid >> 2, wc = wid & 3;
    const int lmro = (lane & 7) + ((lane >> 3) & 1) * 8;
    const int lmco = (lane >> 4) * 8;
    const int b_nt = (lane >> 4), b_kh = (lane >> 3) & 1;
    const int b_ro = lane & 7;
    const int lrow = tid >> 2, loc = tid & 3;   // cp.async mapping

    const uint32_t smb = smem_u32(smem);

    auto issue = [&](int s) {
        const int k0 = s * 32;
        const uint32_t st = smb + (s % 3) * (STAGE_H * 2);
#pragma unroll
        for (int i = 0; i < 2; i++) {
            int row = lrow + i * 64;
            CP_ASYNC16(st + 2 * (row * GPH + loc * 8),
                       A + (size_t)(m0 + row) * EMB + k0 + loc * 8);
            CP_ASYNC16(st + 2 * (128 * GPH + row * GPH + loc * 8),
                       B + (size_t)(n0 + row) * EMB + k0 + loc * 8);
        }
        CP_COMMIT();
    };

    issue(0);
    issue(1);

    for (int s = 0; s < NST; s++) {
        if (s + 2 < NST) { CP_WAIT(1); } else { CP_WAIT(0); }
        __syncthreads();
        if (s + 2 < NST) issue(s + 2);

        const uint32_t st = smb + (s % 3) * (STAGE_H * 2);
        const uint32_t a_base = st + 2 * ((wr * 64 + lmro) * GPH + lmco);
        const uint32_t b_base = st + 2 * (128 * GPH +
                                (wc * 32 + b_nt * 8 + b_ro) * GPH + b_kh * 8);
#pragma unroll
        for (int ks = 0; ks < 2; ks++) {
            const int k0 = ks * 16;
            uint32_t af[4][4], bf[4][2];
#pragma unroll
            for (int mt = 0; mt < 4; mt++)
                ldmatrix_x4(af[mt], a_base + 2 * (mt * 16 * GPH + k0));
#pragma unroll
            for (int p = 0; p < 2; p++) {
                uint32_t r[4];
                ldmatrix_x4(r, b_base + 2 * (p * 16 * GPH + k0));
                bf[2 * p][0] = r[0];     bf[2 * p][1] = r[1];
                bf[2 * p + 1][0] = r[2]; bf[2 * p + 1][1] = r[3];
            }
#pragma unroll
            for (int mt = 0; mt < 4; mt++)
#pragma unroll
                for (int nt = 0; nt < 4; nt++)
                    mma_f16(acc[mt][nt], af[mt], bf[nt]);
        }
    }
}

// QKV projection: half in/out, Q scaled by (1/8)*log2(e) in epilogue
// (attention softmax runs in the exp2 domain).
__global__ __launch_bounds__(256) void gemm_qkv(
    const float* __restrict__ bQ, const float* __restrict__ bK,
    const float* __restrict__ bV)
{
    extern __shared__ __half smem[];
    const __half* Bm = (blockIdx.z == 0) ? g_wq : (blockIdx.z == 1) ? g_wk : g_wv;
    const float* bias = (blockIdx.z == 0) ? bQ : (blockIdx.z == 1) ? bK : bV;
    __half* C = (blockIdx.z == 0) ? g_q : (blockIdx.z == 1) ? g_k : g_v;
    const float qs = (blockIdx.z == 0) ? 0.125f * 1.44269504f : 1.0f;
    const int m0 = blockIdx.y * 128, n0 = blockIdx.x * 128;

    float acc[4][4][4];
#pragma unroll
    for (int mt = 0; mt < 4; mt++)
#pragma unroll
        for (int nt = 0; nt < 4; nt++)
#pragma unroll
            for (int i = 0; i < 4; i++) acc[mt][nt][i] = 0.f;

    gemm_body(g_x, Bm, smem, acc, m0, n0);

    const int lane = threadIdx.x & 31, wid = threadIdx.x >> 5;
    const int wr = wid >> 2, wc = wid & 3;
    const int gr = lane >> 2, tg = lane & 3;
#pragma unroll
    for (int mt = 0; mt < 4; mt++)
#pragma unroll
        for (int nt = 0; nt < 4; nt++) {
            int r = m0 + wr * 64 + mt * 16 + gr;
            int c = n0 + wc * 32 + nt * 8 + tg * 2;
            float b0 = bias[c], b1 = bias[c + 1];
            *(uint32_t*)&C[(size_t)r * EMB + c] =
                packh2((acc[mt][nt][0] + b0) * qs, (acc[mt][nt][1] + b1) * qs);
            *(uint32_t*)&C[(size_t)(r + 8) * EMB + c] =
                packh2((acc[mt][nt][2] + b0) * qs, (acc[mt][nt][3] + b1) * qs);
        }
}

// Output projection: z (half) @ WO^T -> fp32 out + bias.
__global__ __launch_bounds__(256) void gemm_wo(
    const float* __restrict__ bias, float* __restrict__ C)
{
    extern __shared__ __half smem[];
    const int m0 = blockIdx.y * 128, n0 = blockIdx.x * 128;

    float acc[4][4][4];
#pragma unroll
    for (int mt = 0; mt < 4; mt++)
#pragma unroll
        for (int nt = 0; nt < 4; nt++)
#pragma unroll
            for (int i = 0; i < 4; i++) acc[mt][nt][i] = 0.f;

    gemm_body(g_z, g_wo, smem, acc, m0, n0);

    const int lane = threadIdx.x & 31, wid = threadIdx.x >> 5;
    const int wr = wid >> 2, wc = wid & 3;
    const int gr = lane >> 2, tg = lane & 3;
#pragma unroll
    for (int mt = 0; mt < 4; mt++)
#pragma unroll
        for (int nt = 0; nt < 4; nt++) {
            int r = m0 + wr * 64 + mt * 16 + gr;
            int c = n0 + wc * 32 + nt * 8 + tg * 2;
            float b0 = bias[c], b1 = bias[c + 1];
            *(float2*)(C + (size_t)r * EMB + c) =
                make_float2(acc[mt][nt][0] + b0, acc[mt][nt][1] + b1);
            *(float2*)(C + (size_t)(r + 8) * EMB + c) =
                make_float2(acc[mt][nt][2] + b0, acc[mt][nt][3] + b1);
        }
}

// ===========================================================================
// Flash attention (causal), fp16 m16n8k16, register softmax in exp2 domain,
// all-ldmatrix, 3-STAGE cp.async ring of 32-key K/V tiles (wait_group 1 ->
// loads 2 tiles deep, wait nearly always satisfied).
// Block = (b, head, 128-query tile), 128 thr, 4 warps.
// ===========================================================================
#define AP 72   // half pitch (144B = 9x16B)

__global__ __launch_bounds__(128) void attn_tc()
{
    __shared__ __half sbuf[192 * AP];   // 27.6 KB: 3 x (32K + 32V) buffers
    const __half* q = g_q; const __half* k = g_k; const __half* v = g_v;

    const int tid = threadIdx.x;
    const int w = tid >> 5, lane = tid & 31;
    const int gr = lane >> 2, tg = lane & 3;
    const int qt = gridDim.x - 1 - blockIdx.x;      // LPT: big tiles first
    const int hn = blockIdx.y, b = blockIdx.z;
    const int q_base = qt * 128;
    const size_t base_bn = (size_t)b * SEQ * EMB + (size_t)hn * HDIM;

    const int lmro = (lane & 7) + ((lane >> 3) & 1) * 8;
    const int lmco = (lane >> 4) * 8;
    const int b_nt = (lane >> 4), b_kh = (lane >> 3) & 1;
    const int b_ro = lane & 7;

    // ---- Q phase: gmem -> smem (rows 0..127 of sbuf) -> A-frags ----
#pragma unroll
    for (int i = 0; i < 8; i++) {
        int idx = tid + i * 128;
        int row = idx >> 3, oc = idx & 7;
        *(uint4*)&sbuf[row * AP + oc * 8] =
            *(const uint4*)(q + base_bn + (size_t)(q_base + row) * EMB + oc * 8);
    }
    __syncthreads();
    uint32_t qf[2][4][4];
    {
        const uint32_t qb = smem_u32(sbuf) + 2 * ((w * 32 + lmro) * AP + lmco);
#pragma unroll
        for (int mt = 0; mt < 2; mt++)
#pragma unroll
            for (int ks = 0; ks < 4; ks++)
                ldmatrix_x4(qf[mt][ks], qb + 2 * (mt * 16 * AP + ks * 16));
    }
    __syncthreads();

    const uint32_t sbu = smem_u32(sbuf);
    const int cprow = tid >> 2, cpoc = tid & 3;   // cp.async mapping
    const int lm_row = ((lane >> 3) & 1) * 8 + (lane & 7);
    const int lm_col = (lane >> 4) * 8;

    const int wrow = q_base + w * 32;
    const int nkt = 4 * qt + 4;

    auto issue_kv = [&](int kt) {
        const uint32_t kd = sbu + (kt % 3) * (64 * AP * 2);
        const uint32_t vd = kd + 32 * AP * 2;
        const size_t g = base_bn + (size_t)(kt * 32 + cprow) * EMB;
#pragma unroll
        for (int i = 0; i < 2; i++) {
            int c = cpoc + i * 4;
            CP_ASYNC16(kd + 2 * (cprow * AP + c * 8), k + g + c * 8);
            CP_ASYNC16(vd + 2 * (cprow * AP + c * 8), v + g + c * 8);
        }
        CP_COMMIT();
    };

    float o[2][8][4];
#pragma unroll
    for (int mt = 0; mt < 2; mt++)
#pragma unroll
        for (int nt = 0; nt < 8; nt++)
#pragma unroll
            for (int i = 0; i < 4; i++) o[mt][nt][i] = 0.f;

    float mX[2][2] = {{-INFINITY, -INFINITY}, {-INFINITY, -INFINITY}};
    float lX[2][2] = {{0.f, 0.f}, {0.f, 0.f}};

    issue_kv(0);
    if (nkt > 1) issue_kv(1);

    for (int kt = 0; kt < nkt; kt++) {
        if (kt + 2 < nkt) { CP_WAIT(1); } else { CP_WAIT(0); }
        __syncthreads();
        if (kt + 2 < nkt) issue_kv(kt + 2);

        if (kt * 32 <= wrow + 31) {   // warp-uniform causal skip
            const uint32_t kbase = sbu + (kt % 3) * (64 * AP * 2);
            const uint32_t ks_frag_base =
                kbase + 2 * ((b_nt * 8 + b_ro) * AP + b_kh * 8);
            const uint32_t vs_base = kbase + 2 * (32 * AP);

            // ---- scores ----
            float sc[2][4][4];
#pragma unroll
            for (int mt = 0; mt < 2; mt++)
#pragma unroll
                for (int nt = 0; nt < 4; nt++)
#pragma unroll
                    for (int i = 0; i < 4; i++) sc[mt][nt][i] = 0.f;
#pragma unroll
            for (int ks = 0; ks < 4; ks++) {
                uint32_t bf[4][2];
#pragma unroll
                for (int p = 0; p < 2; p++) {
                    uint32_t r[4];
                    ldmatrix_x4(r, ks_frag_base + 2 * (p * 16 * AP + ks * 16));
                    bf[2 * p][0] = r[0];     bf[2 * p][1] = r[1];
                    bf[2 * p + 1][0] = r[2]; bf[2 * p + 1][1] = r[3];
                }
#pragma unroll
                for (int nt = 0; nt < 4; nt++) {
                    mma_f16(sc[0][nt], qf[0][ks], bf[nt]);
                    mma_f16(sc[1][nt], qf[1][ks], bf[nt]);
                }
            }

            // ---- causal mask ----
            if (kt * 32 + 31 > wrow) {
#pragma unroll
                for (int mt = 0; mt < 2; mt++) {
                    const int ig0 = wrow + mt * 16 + gr;
                    const int ig1 = ig0 + 8;
                    const int jb = kt * 32 + tg * 2;
#pragma unroll
                    for (int nt = 0; nt < 4; nt++) {
                        int jg = jb + nt * 8;
                        if (jg > ig0)     sc[mt][nt][0] = -1e30f;
                        if (jg + 1 > ig0) sc[mt][nt][1] = -1e30f;
                        if (jg > ig1)     sc[mt][nt][2] = -1e30f;
                        if (jg + 1 > ig1) sc[mt][nt][3] = -1e30f;
                    }
                }
            }

            // ---- online softmax per m-tile (exp2 domain) ----
            const unsigned FULL = 0xffffffffu;
            float aa[2][2];
#pragma unroll
            for (int mt = 0; mt < 2; mt++) {
                float tm0 = sc[mt][0][0], tm1 = sc[mt][0][2];
#pragma unroll
                for (int nt = 0; nt < 4; nt++) {
                    tm0 = fmaxf(tm0, fmaxf(sc[mt][nt][0], sc[mt][nt][1]));
                    tm1 = fmaxf(tm1, fmaxf(sc[mt][nt][2], sc[mt][nt][3]));
                }
                tm0 = fmaxf(tm0, __shfl_xor_sync(FULL, tm0, 1));
                tm0 = fmaxf(tm0, __shfl_xor_sync(FULL, tm0, 2));
                tm1 = fmaxf(tm1, __shfl_xor_sync(FULL, tm1, 1));
                tm1 = fmaxf(tm1, __shfl_xor_sync(FULL, tm1, 2));

                float mn0 = fmaxf(mX[mt][0], tm0), mn1 = fmaxf(mX[mt][1], tm1);
                float a0 = ex2f(mX[mt][0] - mn0), a1 = ex2f(mX[mt][1] - mn1);
                mX[mt][0] = mn0; mX[mt][1] = mn1;

                float s0 = 0.f, s1 = 0.f;
#pragma unroll
                for (int nt = 0; nt < 4; nt++) {
                    float p00 = ex2f(sc[mt][nt][0] - mn0);
                    float p01 = ex2f(sc[mt][nt][1] - mn0);
                    float p10 = ex2f(sc[mt][nt][2] - mn1);
                    float p11 = ex2f(sc[mt][nt][3] - mn1);
                    s0 += p00 + p01; s1 += p10 + p11;
                    sc[mt][nt][0] = p00; sc[mt][nt][1] = p01;
                    sc[mt][nt][2] = p10; sc[mt][nt][3] = p11;
                }
                s0 += __shfl_xor_sync(FULL, s0, 1);
                s0 += __shfl_xor_sync(FULL, s0, 2);
                s1 += __shfl_xor_sync(FULL, s1, 1);
                s1 += __shfl_xor_sync(FULL, s1, 2);
                lX[mt][0] = lX[mt][0] * a0 + s0;
                lX[mt][1] = lX[mt][1] * a1 + s1;
                aa[mt][0] = a0; aa[mt][1] = a1;
            }

            // ---- rescale O ----
#pragma unroll
            for (int mt = 0; mt < 2; mt++)
#pragma unroll
                for (int nt = 0; nt < 8; nt++) {
                    o[mt][nt][0] *= aa[mt][0]; o[mt][nt][1] *= aa[mt][0];
                    o[mt][nt][2] *= aa[mt][1]; o[mt][nt][3] *= aa[mt][1];
                }

            // ---- O += P @ V ----
#pragma unroll
            for (int kg = 0; kg < 2; kg++) {
                uint32_t af[2][4];
#pragma unroll
                for (int mt = 0; mt < 2; mt++) {
                    af[mt][0] = packh2(sc[mt][2 * kg][0], sc[mt][2 * kg][1]);
                    af[mt][1] = packh2(sc[mt][2 * kg][2], sc[mt][2 * kg][3]);
                    af[mt][2] = packh2(sc[mt][2 * kg + 1][0], sc[mt][2 * kg + 1][1]);
                    af[mt][3] = packh2(sc[mt][2 * kg + 1][2], sc[mt][2 * kg + 1][3]);
                }
                const uint32_t rbase =
                    vs_base + 2 * ((kg * 16 + lm_row) * AP + lm_col);
#pragma unroll
                for (int pr = 0; pr < 4; pr++) {
                    uint32_t vb[4];
                    ldmatrix_x4_trans(vb, rbase + 2 * (pr * 16));
                    mma_f16(o[0][2 * pr],     af[0], vb);
                    mma_f16(o[0][2 * pr + 1], af[0], vb + 2);
                    mma_f16(o[1][2 * pr],     af[1], vb);
                    mma_f16(o[1][2 * pr + 1], af[1], vb + 2);
                }
            }
        }
    }

    // ---- normalize & store (half) ----
#pragma unroll
    for (int mt = 0; mt < 2; mt++) {
        const float inv0 = 1.f / lX[mt][0], inv1 = 1.f / lX[mt][1];
        const int r0 = wrow + mt * 16 + gr;
#pragma unroll
        for (int nt = 0; nt < 8; nt++) {
            int d = nt * 8 + tg * 2;
            size_t g0 = base_bn + (size_t)r0 * EMB + d;
            size_t g1 = base_bn + (size_t)(r0 + 8) * EMB + d;
            *(uint32_t*)&g_z[g0] = packh2(o[mt][nt][0] * inv0, o[mt][nt][1] * inv0);
            *(uint32_t*)&g_z[g1] = packh2(o[mt][nt][2] * inv1, o[mt][nt][3] * inv1);
        }
    }
}

// ---------------------------------------------------------------------------
extern "C" void kernel_launch(void* const* d_in, const int* in_sizes, int n_in,
                              void* d_out, int out_size)
{
    const float* x  = (const float*)d_in[0];
    const float* WQ = (const float*)d_in[1];
    const float* WK = (const float*)d_in[2];
    const float* WV = (const float*)d_in[3];
    const float* WO = (const float*)d_in[4];
    const float* bQ = (const float*)d_in[5];
    const float* bK = (const float*)d_in[6];
    const float* bV = (const float*)d_in[7];
    const float* bO = (const float*)d_in[8];
    float* out = (float*)d_out;

    __half *wqp, *wkp, *wvp;
    cudaGetSymbolAddress((void**)&wqp, g_wq);
    cudaGetSymbolAddress((void**)&wkp, g_wk);
    cudaGetSymbolAddress((void**)&wvp, g_wv);

    cudaFuncSetAttribute(gemm_qkv,
        cudaFuncAttributeMaxDynamicSharedMemorySize, GEMM_SMEM);
    cudaFuncSetAttribute(gemm_wo,
        cudaFuncAttributeMaxDynamicSharedMemorySize, GEMM_SMEM);

    // ---- prep: convert x, transpose+convert weights ----
    cvt_x<<<BS_TOT * EMB / 4 / 256, 256>>>(x);
    tr_qkv<<<dim3(2, 24, 12), dim3(32, 8)>>>(WQ, wqp);
    tr_qkv<<<dim3(2, 24, 12), dim3(32, 8)>>>(WK, wkp);
    tr_qkv<<<dim3(2, 24, 12), dim3(32, 8)>>>(WV, wvp);
    tr_wo<<<dim3(24, 24), dim3(32, 8)>>>(WO);

    // ---- main pipeline ----
    gemm_qkv<<<dim3(EMB / 128, BS_TOT / 128, 3), 256, GEMM_SMEM>>>(bQ, bK, bV);
    attn_tc<<<dim3(SEQ / 128, NHEADS, BATCH), 128>>>();
    gemm_wo<<<dim3(EMB / 128, BS_TOT / 128), 256, GEMM_SMEM>>>(bO, out);
}